// round 17
// baseline (speedup 1.0000x reference)
#include <cuda_runtime.h>
#include <cuda_bf16.h>

// Problem constants
#define NB 4
#define NC 64
#define NH 128
#define NW 128
#define NN 16
#define NPIX (NB*NH*NW)   // 65536 pixels

typedef unsigned long long u64;

// Scratch (allocation-free rule: __device__ globals)
static __device__ float g_delta[(size_t)NPIX*64];   // [p][c]
static __device__ float g_u[(size_t)NPIX*64];       // [p][c]
static __device__ float g_Bc[(size_t)NPIX*16];      // [p][n]
static __device__ float g_Cc[(size_t)NPIX*16];      // [p][n]
static __device__ float g_yh[(size_t)NPIX*64];      // [p][c]
static __device__ float g_yv[(size_t)NPIX*64];      // [p][c]

__device__ __forceinline__ float fexp2(float x) {
    float r;
    asm("ex2.approx.f32 %0, %1;" : "=f"(r) : "f"(x));
    return r;
}
__device__ __forceinline__ u64 pack2(float lo, float hi) {
    u64 r; asm("mov.b64 %0, {%1, %2};" : "=l"(r) : "f"(lo), "f"(hi)); return r;
}
__device__ __forceinline__ void unpack2(u64 v, float& lo, float& hi) {
    asm("mov.b64 {%0, %1}, %2;" : "=f"(lo), "=f"(hi) : "l"(v));
}
__device__ __forceinline__ u64 fma2(u64 a, u64 b, u64 c) {
    u64 d; asm("fma.rn.f32x2 %0, %1, %2, %3;" : "=l"(d) : "l"(a), "l"(b), "l"(c)); return d;
}
__device__ __forceinline__ u64 mul2(u64 a, u64 b) {
    u64 d; asm("mul.rn.f32x2 %0, %1, %2;" : "=l"(d) : "l"(a), "l"(b)); return d;
}

// ---------------------------------------------------------------------------
// Projection v7: as v5 (512 rows x 2 output-halves, 128-thread blocks,
// 7/SM => one wave) but with the folded weights stored PERMUTED so each
// thread's 6 weights are contiguous: slot(o) = (o&7)*8 + (o>>3). Per k the
// weight fetch is 1 LDS.128 + 1 LDS.64 instead of 6 scalar LDS.
// x tile processed in 4 quarters of 16 channels to keep smem ~25KB.
// ---------------------------------------------------------------------------
#define X_STRIDE  130   // s_x row pad ([k][128 pix]), even => 8B aligned

__global__ __launch_bounds__(128, 7) void proj_kernel(const float* __restrict__ x,
                                                      const float* __restrict__ xw,   // [36,64]
                                                      const float* __restrict__ dtw,  // [64,4]
                                                      const float* __restrict__ dtb)  // [64]
{
    __shared__ __align__(16) float s_wt[64*64];      // [k][slot]; reused as staging
    __shared__ __align__(16) float s_x[16*X_STRIDE]; // [k-quarter][pix]
    __shared__ float s_bias[64];

    int blk = blockIdx.x;          // 0..1023
    int bh  = blk >> 1;            // row 0..511
    int og  = blk & 1;             // output half
    int b   = bh >> 7;
    int h   = bh & 127;
    int tid = threadIdx.x;
    int tx  = tid & 15;            // pixel-pair group
    int ty  = tid >> 4;            // 0..7

    // Fold weights for this block's 48 output rows; store [k][slot] with
    // slot = (o_local & 7)*8 + (o_local >> 3) so thread ty's 6 weights are
    // contiguous at [k][ty*8 .. ty*8+5].
    for (int i = tid; i < 48*64; i += 128) {
        int rl = i >> 6, c = i & 63;
        int r  = og*48 + rl;
        float v;
        if (r < 64) {
            v = dtw[r*4+0]*xw[0*64+c] + dtw[r*4+1]*xw[1*64+c]
              + dtw[r*4+2]*xw[2*64+c] + dtw[r*4+3]*xw[3*64+c];
        } else {
            v = xw[(r - 60)*64 + c];
        }
        int slot = (rl & 7)*8 + (rl >> 3);
        s_wt[c*64 + slot] = v;
    }
    if (tid < 64) s_bias[tid] = dtb[tid];

    size_t pbase = (size_t)bh * 128;

    u64 acc2[6][4];
    #pragma unroll
    for (int i = 0; i < 6; i++)
        #pragma unroll
        for (int jp = 0; jp < 4; jp++) acc2[i][jp] = 0ull;

    for (int q = 0; q < 4; q++) {
        __syncthreads();   // q 0: also covers weight-fold completion
        // Load x quarter: 16 channels x 128 pixels, coalesced rows
        #pragma unroll
        for (int it = 0; it < 16; it++) {
            int idx = it*128 + tid;
            int cl  = idx >> 7;      // 0..15
            int w   = idx & 127;
            s_x[cl*X_STRIDE + w] =
                x[(((size_t)(b*64 + q*16 + cl))*128 + h)*128 + w];
        }
        __syncthreads();

        // og==0 block also emits the u transpose [p][c] (coalesced 64B rows)
        if (og == 0) {
            #pragma unroll
            for (int it = 0; it < 16; it++) {
                int idx = it*128 + tid;
                int pix = idx >> 4;
                int c   = idx & 15;
                g_u[(pbase + pix)*64 + q*16 + c] = s_x[c*X_STRIDE + pix];
            }
        }

        // GEMM mainloop over this quarter's 16 channels.
        // Per k: 1 LDS.128 + 1 LDS.64 (weights) + 4 LDS.64 (x) -> 24 FFMA2.
        #pragma unroll 4
        for (int k = 0; k < 16; k++) {
            const float* wrow = s_wt + (q*16 + k)*64 + ty*8;
            float4 wq = *(const float4*)(wrow);
            float2 wd = *(const float2*)(wrow + 4);
            u64 w2[6];
            w2[0] = pack2(wq.x, wq.x);
            w2[1] = pack2(wq.y, wq.y);
            w2[2] = pack2(wq.z, wq.z);
            w2[3] = pack2(wq.w, wq.w);
            w2[4] = pack2(wd.x, wd.x);
            w2[5] = pack2(wd.y, wd.y);
            u64 xp[4];
            #pragma unroll
            for (int jp = 0; jp < 4; jp++)
                xp[jp] = *(const u64*)(s_x + k*X_STRIDE + 2*tx + 32*jp);
            #pragma unroll
            for (int i = 0; i < 6; i++)
                #pragma unroll
                for (int jp = 0; jp < 4; jp++)
                    acc2[i][jp] = fma2(w2[i], xp[jp], acc2[i][jp]);
        }
    }

    __syncthreads();

    // Epilogue: 3 chunks of 16 outputs; stage [pix][j] in smem (reuse s_wt).
    // acc2[cch*2+ii] maps to o_local = cch*16 + (ty + 8*ii)  (same as v5).
    float* s_st = s_wt;
    for (int cch = 0; cch < 3; cch++) {
        #pragma unroll
        for (int jp = 0; jp < 4; jp++) {
            #pragma unroll
            for (int ii = 0; ii < 2; ii++) {
                float lo, hi; unpack2(acc2[cch*2 + ii][jp], lo, hi);
                int pp = 2*tx + 32*jp;
                s_st[pp*17 + ty + 8*ii]       = lo;
                s_st[(pp + 1)*17 + ty + 8*ii] = hi;
            }
        }
        __syncthreads();
        #pragma unroll
        for (int it = 0; it < 16; it++) {
            int idx = it*128 + tid;
            int pix = idx >> 4;
            int j   = idx & 15;
            float v = s_st[pix*17 + j];
            int o   = og*48 + cch*16 + j;
            if (o < 64) {
                v += s_bias[o];
                v = (v > 15.f) ? v : __logf(1.f + __expf(v));   // softplus
                g_delta[(pbase + pix)*64 + o] = v;
            } else if (o < 80) {
                g_Bc[(pbase + pix)*16 + (o - 64)] = v;
            } else {
                g_Cc[(pbase + pix)*16 + (o - 80)] = v;
            }
        }
        __syncthreads();
    }
}

// ---------------------------------------------------------------------------
// Scan v7: half-split layout; ALL operands (delta, u, B, C) staged through
// double-buffered smem in 16-iteration chunks. Zero LDG in the inner loop;
// per chunk each thread issues 5 coalesced LDG.128s.
// One sequence per 128-thread block; blocks 0..511 H, 512..1023 V.
// ---------------------------------------------------------------------------
__global__ __launch_bounds__(128) void scan_kernel(const float* __restrict__ A_log)
{
    __shared__ __align__(16) float s_d[2][16*64];   // [buf][iter][c]
    __shared__ __align__(16) float s_u[2][16*64];
    __shared__ __align__(16) float s_B[2][16*16];   // [buf][iter][n]
    __shared__ __align__(16) float s_C[2][16*16];

    int tid  = threadIdx.x;
    int d    = tid >> 1;          // channel 0..63
    int half = tid & 1;           // state group (0: n=0..7, 1: n=8..15)
    int blk  = blockIdx.x;        // 0..1023
    int dir  = blk >> 9;          // 0 = H, 1 = V
    int s    = blk & 511;
    int b    = s >> 7;
    int rc   = s & 127;

    size_t pix0;
    int stride;
    float* __restrict__ yout;
    if (dir == 0) { pix0 = ((size_t)(b*128 + rc))*128; stride = 1;   yout = g_yh; }
    else          { pix0 = (size_t)b*16384 + rc;       stride = 128; yout = g_yv; }

    u64 A22[4];
    #pragma unroll
    for (int q = 0; q < 4; q++) {
        const float* ap = A_log + d*16 + half*8 + 2*q;
        float a0 = -__expf(ap[0]) * 1.4426950408889634f;
        float a1 = -__expf(ap[1]) * 1.4426950408889634f;
        A22[q] = pack2(a0, a1);
    }

    u64 hs2[4];
    #pragma unroll
    for (int q = 0; q < 4; q++) hs2[q] = 0ull;

    // Cooperative-load indices
    int bc_i = (tid & 63) >> 2;        // B/C: iter
    int bc_j = tid & 3;                // B/C: float4 lane
    const float* bc_src = (tid < 64) ? g_Bc : g_Cc;

    for (int c = 0; c < 8; c++) {
        int buf = c & 1;
        // Stage delta & u: 16 iters x 64 ch = 256 float4; 2 per thread.
        #pragma unroll
        for (int r = 0; r < 2; r++) {
            int idx = r*128 + tid;     // 0..255
            int it  = idx >> 4;        // 0..15
            int g4  = idx & 15;        // float4 group within row
            size_t pp = pix0 + (size_t)(c*16 + it)*stride;
            *(float4*)(s_d[buf] + it*64 + g4*4) =
                *(const float4*)(g_delta + pp*64 + g4*4);
            *(float4*)(s_u[buf] + it*64 + g4*4) =
                *(const float4*)(g_u + pp*64 + g4*4);
        }
        // Stage B/C: threads 0..63 -> B, 64..127 -> C.
        {
            size_t pp = pix0 + (size_t)(c*16 + bc_i)*stride;
            float* dst = ((tid < 64) ? s_B[buf] : s_C[buf]) + bc_i*16 + bc_j*4;
            *(float4*)dst = *(const float4*)(bc_src + pp*16 + bc_j*4);
        }
        __syncthreads();

        const float* dbuf = s_d[buf];
        const float* ubuf = s_u[buf];
        const float* bbuf = s_B[buf];
        const float* cbuf = s_C[buf];

        #pragma unroll
        for (int i = 0; i < 16; i++) {
            int l = c*16 + i;
            size_t p = pix0 + (size_t)l*stride;

            float delta = dbuf[i*64 + d];
            float uu    = ubuf[i*64 + d];
            ulonglong2 Bv = *(const ulonglong2*)(bbuf + i*16 + half*8);
            ulonglong2 Cv = *(const ulonglong2*)(cbuf + i*16 + half*8);
            ulonglong2 Bw = *(const ulonglong2*)(bbuf + i*16 + half*8 + 4);
            ulonglong2 Cw = *(const ulonglong2*)(cbuf + i*16 + half*8 + 4);

            float du = delta * uu;
            u64 du2 = pack2(du, du);
            u64 delta2 = pack2(delta, delta);
            u64 y2 = 0ull;

#define SSM_STEP2(q, bv, cv)                                       \
            {                                                      \
                u64 e2 = mul2(delta2, A22[q]);                     \
                float e0, e1; unpack2(e2, e0, e1);                 \
                u64 dA2 = pack2(fexp2(e0), fexp2(e1));             \
                hs2[q] = fma2(dA2, hs2[q], mul2(du2, (bv)));       \
                y2 = fma2(hs2[q], (cv), y2);                       \
            }
            SSM_STEP2(0, Bv.x, Cv.x);
            SSM_STEP2(1, Bv.y, Cv.y);
            SSM_STEP2(2, Bw.x, Cw.x);
            SSM_STEP2(3, Bw.y, Cw.y);
#undef SSM_STEP2

            float ylo, yhi; unpack2(y2, ylo, yhi);
            float y = ylo + yhi;
            y += __shfl_xor_sync(0xffffffffu, y, 1);
            if (half == 0) yout[p*64 + d] = y;
        }
    }
}

// ---------------------------------------------------------------------------
// Combine + transpose (unchanged)
// ---------------------------------------------------------------------------
__global__ __launch_bounds__(256) void combine_kernel(const float* __restrict__ x,
                                                      const float* __restrict__ Dv,
                                                      float* __restrict__ out)
{
    __shared__ float s[32][33];
    int t    = blockIdx.x;
    int tile = t & 7;
    int bh   = t >> 3;
    int b    = bh >> 7;
    int h    = bh & 127;
    int c0   = (tile & 1) * 32;
    int w0   = (tile >> 1) * 32;
    size_t pbase = (size_t)bh * 128;

    {
        int row = threadIdx.x >> 3;
        int cg  = threadIdx.x & 7;
        size_t idx = (pbase + w0 + row)*64 + c0 + cg*4;
        float4 a = *(const float4*)(g_yh + idx);
        float4 v = *(const float4*)(g_yv + idx);
        s[row][cg*4+0] = a.x + v.x;
        s[row][cg*4+1] = a.y + v.y;
        s[row][cg*4+2] = a.z + v.z;
        s[row][cg*4+3] = a.w + v.w;
    }
    __syncthreads();

    int tx = threadIdx.x & 31;
    int ty = threadIdx.x >> 5;
    #pragma unroll
    for (int i = 0; i < 4; i++) {
        int ci = ty + i*8;
        int c  = c0 + ci;
        size_t xi = (((size_t)(b*64 + c))*128 + h)*128 + w0 + tx;
        out[xi] = s[tx][ci] + 2.f * Dv[c] * x[xi];
    }
}

// ---------------------------------------------------------------------------
extern "C" void kernel_launch(void* const* d_in, const int* in_sizes, int n_in,
                              void* d_out, int out_size)
{
    const float* x     = (const float*)d_in[0];   // [4,64,128,128]
    const float* A_log = (const float*)d_in[1];   // [64,16]
    const float* Dv    = (const float*)d_in[2];   // [64]
    const float* xw    = (const float*)d_in[3];   // [36,64]
    const float* dtw   = (const float*)d_in[4];   // [64,4]
    const float* dtb   = (const float*)d_in[5];   // [64]
    float* out = (float*)d_out;

    proj_kernel<<<NB*NH*2, 128>>>(x, xw, dtw, dtb);
    scan_kernel<<<1024, 128>>>(A_log);
    combine_kernel<<<NB*NH*8, 256>>>(x, Dv, out);
}